// round 17
// baseline (speedup 1.0000x reference)
#include <cuda_runtime.h>
#include <cstdint>

// Problem constants (fixed shapes for this problem instance)
#define GN   100000      // nodes
#define GE   1600000     // edges
#define GEL  200000      // link-pred edges
#define INC  64
#define POSC 16
#define KH   80          // INC + POSC
#define HID  64
#define OUTC 32
#define NB   98          // scan blocks: ceil(GN / 1024)

// ---------------- scratch (device globals; no allocation allowed) -----------
__device__ float g_dinv[GN];
__device__ float g_hw1 [GN * HID];
__device__ float g_agg1[GN * HID];
__device__ float g_hw2 [GN * OUTC];
__device__ int   g_cnt [GN];        // degree; zeroed by k_fill for next call
__device__ int   g_cur [GN];        // scatter cursor
__device__ int   g_bsum[128];
__device__ int   g_bscan[128];
__device__ int   g_csrc[GE];        // dst-sorted edge list: src
__device__ int   g_cdst[GE];        // dst-sorted edge list: dst
__device__ float g_cnrm[GE];        // dst-sorted edge list: dinv[s]*dinv[d]

// component select (compile-time under full unroll)
__device__ __forceinline__ float f4c(const float4& v, int kk) {
    return kk == 0 ? v.x : kk == 1 ? v.y : kk == 2 ? v.z : v.w;
}

// ---------------- degree histogram ------------------------------------------
__global__ void k_hist(const int* __restrict__ dst, int* cnt) {
    int i = blockIdx.x * blockDim.x + threadIdx.x;
    if (i < GE) atomicAdd(&cnt[dst[i]], 1);
}

// ---------------- exclusive scan of cnt -> cur (3 kernels, residency-safe) ---
__global__ void k_scan_local(const int* __restrict__ cnt, int* off, int* bsum) {
    __shared__ int s[256];
    const int b = blockIdx.x, t = threadIdx.x;
    const int i0 = b * 1024 + t * 4;
    int v[4]; int sum = 0;
#pragma unroll
    for (int j = 0; j < 4; j++) {
        int idx = i0 + j;
        int c = (idx < GN) ? cnt[idx] : 0;
        v[j] = sum; sum += c;
    }
    s[t] = sum;
    __syncthreads();
    for (int d = 1; d < 256; d <<= 1) {
        int x = (t >= d) ? s[t - d] : 0;
        __syncthreads();
        s[t] += x;
        __syncthreads();
    }
    int base = (t > 0) ? s[t - 1] : 0;
#pragma unroll
    for (int j = 0; j < 4; j++) {
        int idx = i0 + j;
        if (idx < GN) off[idx] = base + v[j];
    }
    if (t == 255) bsum[b] = s[255];
}

__global__ void k_scan_bsum(const int* __restrict__ bsum, int* bscan) {
    __shared__ int s[128];
    int t = threadIdx.x;
    s[t] = (t < NB) ? bsum[t] : 0;
    __syncthreads();
    for (int d = 1; d < 128; d <<= 1) {
        int x = (t >= d) ? s[t - d] : 0;
        __syncthreads();
        s[t] += x;
        __syncthreads();
    }
    if (t < NB) bscan[t] = (t > 0) ? s[t - 1] : 0;
}

// scan finalize + dinv fused
__global__ void k_scan_add(int* cur, const int* __restrict__ bscan,
                           const int* __restrict__ cnt, float* dinv) {
    const int b = blockIdx.x, t = threadIdx.x;
    const int add = bscan[b];
    const int i0 = b * 1024 + t * 4;
#pragma unroll
    for (int j = 0; j < 4; j++) {
        int idx = i0 + j;
        if (idx < GN) {
            cur[idx] += add;
            dinv[idx] = rsqrtf((float)(cnt[idx] + 1));   // +1 self-loop
        }
    }
}

// ---------------- fill dst-sorted edge list (+ re-zero cnt for next call) ----
__global__ void k_fill(const int* __restrict__ src, const int* __restrict__ dst,
                       const float* __restrict__ dinv,
                       int* cur, int* cnt, int* csrc, int* cdst, float* cnrm) {
    int e = blockIdx.x * blockDim.x + threadIdx.x;
    if (e < GN) cnt[e] = 0;                       // cnt dead after scan; reset invariant
    if (e >= GE) return;
    int s = __ldg(&src[e]);
    int d = __ldg(&dst[e]);
    int p = atomicAdd(&cur[d], 1);
    csrc[p] = s;
    cdst[p] = d;
    cnrm[p] = __ldg(&dinv[s]) * __ldg(&dinv[d]);
}

// ---------------- GEMM 1: hw1 = [x | pos] @ W1  (K=80, Nout=64) -------------
#define KHP  84
#define G1_ROWS 64
__global__ __launch_bounds__(256) void k_gemm1(
    const float* __restrict__ x, const float* __restrict__ pos,
    const float* __restrict__ W1, float* __restrict__ hw1)
{
    __shared__ __align__(16) float sW[KH * HID];          // 20 KB
    __shared__ __align__(16) float sX[G1_ROWS * KHP];     // 21.5 KB
    const int t = threadIdx.x;
    const int row0 = blockIdx.x * G1_ROWS;

    for (int i = t; i < KH * HID; i += 256) sW[i] = W1[i];
    for (int i = t; i < G1_ROWS * INC; i += 256) {
        int r = i >> 6, c = i & 63;
        int gr = row0 + r;
        sX[r * KHP + c] = (gr < GN) ? x[gr * INC + c] : 0.0f;
    }
    for (int i = t; i < G1_ROWS * POSC; i += 256) {
        int r = i >> 4, c = i & 15;
        int gr = row0 + r;
        sX[r * KHP + INC + c] = (gr < GN) ? pos[gr * POSC + c] : 0.0f;
    }
    __syncthreads();

    const int tx = t & 15;
    const int ty = t >> 4;
    float acc[4][4];
#pragma unroll
    for (int r = 0; r < 4; r++)
#pragma unroll
        for (int c = 0; c < 4; c++) acc[r][c] = 0.0f;

    for (int k0 = 0; k0 < KH; k0 += 4) {
        float4 xv[4];
#pragma unroll
        for (int r = 0; r < 4; r++)
            xv[r] = *(const float4*)&sX[(ty * 4 + r) * KHP + k0];
#pragma unroll
        for (int kk = 0; kk < 4; kk++) {
            float4 w = *(const float4*)&sW[(k0 + kk) * HID + tx * 4];
#pragma unroll
            for (int r = 0; r < 4; r++) {
                float xs = f4c(xv[r], kk);
                acc[r][0] += xs * w.x; acc[r][1] += xs * w.y;
                acc[r][2] += xs * w.z; acc[r][3] += xs * w.w;
            }
        }
    }
#pragma unroll
    for (int r = 0; r < 4; r++) {
        int gr = row0 + ty * 4 + r;
        if (gr < GN)
            *(float4*)&hw1[gr * HID + tx * 4] =
                make_float4(acc[r][0], acc[r][1], acc[r][2], acc[r][3]);
    }
}

// ---------------- layer-1 agg init: agg1 = b1 + hw1 * dinv^2 ----------------
__global__ void k_init1(const float4* __restrict__ hw, float4* __restrict__ out,
                        const float* __restrict__ b1, const float* __restrict__ dinv)
{
    int i = blockIdx.x * blockDim.x + threadIdx.x;
    if (i >= GN * 16) return;
    int node = i >> 4, q = i & 15;
    float dv = __ldg(&dinv[node]);
    float s = dv * dv;
    float4 v = __ldg(&hw[i]);
    float4 b = __ldg(&((const float4*)b1)[q]);
    out[i] = make_float4(b.x + v.x * s, b.y + v.y * s,
                         b.z + v.z * s, b.w + v.w * s);
}

// ---------------- GEMM 2: hw2 = relu(agg1) @ W2  (K=64, Nout=32) ------------
#define HIDP 68
#define G2_ROWS 128
__global__ __launch_bounds__(256) void k_gemm2(
    const float* __restrict__ h, const float* __restrict__ W2,
    const float* __restrict__ b2, const float* __restrict__ dinv,
    float* __restrict__ hw2, float* __restrict__ z)
{
    __shared__ __align__(16) float sW[HID * OUTC];        // 8 KB
    __shared__ __align__(16) float sH[G2_ROWS * HIDP];    // 34.8 KB
    const int t = threadIdx.x;
    const int row0 = blockIdx.x * G2_ROWS;

    for (int i = t; i < HID * OUTC; i += 256) sW[i] = W2[i];
    for (int i = t; i < G2_ROWS * HID; i += 256) {
        int r = i >> 6, c = i & 63;
        int gr = row0 + r;
        float v = (gr < GN) ? h[gr * HID + c] : 0.0f;
        sH[r * HIDP + c] = v > 0.0f ? v : 0.0f;       // fused ReLU
    }
    __syncthreads();

    const int tx = t & 7;
    const int ty = t >> 3;
    float acc[4][4];
#pragma unroll
    for (int r = 0; r < 4; r++)
#pragma unroll
        for (int c = 0; c < 4; c++) acc[r][c] = 0.0f;

    for (int k0 = 0; k0 < HID; k0 += 4) {
        float4 hv[4];
#pragma unroll
        for (int r = 0; r < 4; r++)
            hv[r] = *(const float4*)&sH[(ty * 4 + r) * HIDP + k0];
#pragma unroll
        for (int kk = 0; kk < 4; kk++) {
            float4 w = *(const float4*)&sW[(k0 + kk) * OUTC + tx * 4];
#pragma unroll
            for (int r = 0; r < 4; r++) {
                float hs = f4c(hv[r], kk);
                acc[r][0] += hs * w.x; acc[r][1] += hs * w.y;
                acc[r][2] += hs * w.z; acc[r][3] += hs * w.w;
            }
        }
    }

    float4 b = __ldg(&((const float4*)b2)[tx]);
#pragma unroll
    for (int r = 0; r < 4; r++) {
        int gr = row0 + ty * 4 + r;
        if (gr < GN) {
            float dv = __ldg(&dinv[gr]);
            float s = dv * dv;
            *(float4*)&hw2[gr * OUTC + tx * 4] =
                make_float4(acc[r][0], acc[r][1], acc[r][2], acc[r][3]);
            *(float4*)&z[gr * OUTC + tx * 4] =
                make_float4(b.x + acc[r][0] * s, b.y + acc[r][1] * s,
                            b.z + acc[r][2] * s, b.w + acc[r][3] * s);
        }
    }
}

// ---------------- segmented edge aggregation over dst-sorted list ------------
template <int LOGQ, int SB>   // LOGQ=4 (64 feats) SB=256 ; LOGQ=3 (32) SB=512
__global__ __launch_bounds__(256) void k_agg_seg(
    const float4* __restrict__ vals, float4* __restrict__ out,
    const int* __restrict__ csrc, const int* __restrict__ cdst,
    const float* __restrict__ cnrm)
{
    __shared__ int   ssrc[SB];
    __shared__ int   sdst[SB];
    __shared__ float snrm[SB];
    const int t = threadIdx.x;
    const int s0 = blockIdx.x * SB;
    for (int i = t; i < SB; i += 256) {
        ssrc[i] = csrc[s0 + i];
        sdst[i] = cdst[s0 + i];
        snrm[i] = cnrm[s0 + i];
    }
    __syncthreads();

    const int q    = t & ((1 << LOGQ) - 1);
    const int base = (t >> LOGQ) * 16;          // window of 16 slots

    int cur = sdst[base];
    float ax = 0.0f, ay = 0.0f, az = 0.0f, aw = 0.0f;
#pragma unroll
    for (int j = 0; j < 16; j++) {
        int sd = sdst[base + j];
        if (sd != cur) {
            float4* p = &out[(cur << LOGQ) + q];
            asm volatile("red.global.add.v4.f32 [%0], {%1,%2,%3,%4};"
                         :: "l"(p), "f"(ax), "f"(ay), "f"(az), "f"(aw)
                         : "memory");
            ax = ay = az = aw = 0.0f;
            cur = sd;
        }
        float nm = snrm[base + j];
        float4 v = __ldg(&vals[(ssrc[base + j] << LOGQ) + q]);
        ax += v.x * nm; ay += v.y * nm; az += v.z * nm; aw += v.w * nm;
    }
    float4* p = &out[(cur << LOGQ) + q];
    asm volatile("red.global.add.v4.f32 [%0], {%1,%2,%3,%4};"
                 :: "l"(p), "f"(ax), "f"(ay), "f"(az), "f"(aw)
                 : "memory");
}

// ---------------- link head (fused): pred = z[s].WlA + z[d].WlB + bl --------
__global__ __launch_bounds__(256) void k_pred(
    const float* __restrict__ z, const float* __restrict__ Wl,
    const float* __restrict__ bl,
    const int* __restrict__ sl, const int* __restrict__ dl,
    float* __restrict__ pred)
{
    __shared__ float sWl[2 * OUTC];
    __shared__ float sbl;
    int t = threadIdx.x;
    if (t < 2 * OUTC) sWl[t] = Wl[t];
    if (t == 2 * OUTC) sbl = bl[0];
    __syncthreads();
    int i = blockIdx.x * blockDim.x + t;
    if (i >= GEL) return;
    const float4* zs = (const float4*)&z[__ldg(&sl[i]) * OUTC];
    const float4* zd = (const float4*)&z[__ldg(&dl[i]) * OUTC];
    float a = 0.0f, b = 0.0f;
#pragma unroll
    for (int q = 0; q < OUTC / 4; q++) {
        float4 vs = __ldg(&zs[q]);
        float4 vd = __ldg(&zd[q]);
        a += vs.x * sWl[q*4+0] + vs.y * sWl[q*4+1]
           + vs.z * sWl[q*4+2] + vs.w * sWl[q*4+3];
        b += vd.x * sWl[OUTC+q*4+0] + vd.y * sWl[OUTC+q*4+1]
           + vd.z * sWl[OUTC+q*4+2] + vd.w * sWl[OUTC+q*4+3];
    }
    pred[i] = a + b + sbl;
}

// ---------------- launch -----------------------------------------------------
extern "C" void kernel_launch(void* const* d_in, const int* in_sizes, int n_in,
                              void* d_out, int out_size)
{
    const float* x    = (const float*)d_in[0];
    const float* pos  = (const float*)d_in[1];
    const float* W1   = (const float*)d_in[2];
    const float* b1   = (const float*)d_in[3];
    const float* W2   = (const float*)d_in[4];
    const float* b2   = (const float*)d_in[5];
    const float* Wl   = (const float*)d_in[6];
    const float* bl   = (const float*)d_in[7];
    const int*   ei   = (const int*)d_in[8];   // [2, E]: src row then dst row
    const int*   eli  = (const int*)d_in[9];   // [2, EL]

    const int* src = ei;
    const int* dst = ei + GE;
    const int* sl  = eli;
    const int* dl  = eli + GEL;

    float* z    = (float*)d_out;               // [N, OUTC]
    float* pred = z + (size_t)GN * OUTC;       // [EL]

    float *dinv, *hw1, *agg1, *hw2, *cnrm;
    int *cnt, *cur, *bsum, *bscan, *csrc, *cdst;
    cudaGetSymbolAddress((void**)&dinv,  g_dinv);
    cudaGetSymbolAddress((void**)&hw1,   g_hw1);
    cudaGetSymbolAddress((void**)&agg1,  g_agg1);
    cudaGetSymbolAddress((void**)&hw2,   g_hw2);
    cudaGetSymbolAddress((void**)&cnt,   g_cnt);
    cudaGetSymbolAddress((void**)&cur,   g_cur);
    cudaGetSymbolAddress((void**)&bsum,  g_bsum);
    cudaGetSymbolAddress((void**)&bscan, g_bscan);
    cudaGetSymbolAddress((void**)&csrc,  g_csrc);
    cudaGetSymbolAddress((void**)&cdst,  g_cdst);
    cudaGetSymbolAddress((void**)&cnrm,  g_cnrm);

    const int B = 256;

    // Fork: CSR build on a side stream, gemm1 (independent) on the main stream.
    // (Same 2-event topology that passed in rounds 9/11/13/14.)
    cudaStream_t side;
    cudaStreamCreateWithFlags(&side, cudaStreamNonBlocking);
    cudaEvent_t evF, evJ;
    cudaEventCreateWithFlags(&evF, cudaEventDisableTiming);
    cudaEventCreateWithFlags(&evJ, cudaEventDisableTiming);

    cudaEventRecord(evF, 0);
    cudaStreamWaitEvent(side, evF, 0);

    // ---- side stream: histogram -> scan(+dinv) -> fill(+cnt reset)
    k_hist<<<(GE + B - 1) / B, B, 0, side>>>(dst, cnt);
    k_scan_local<<<NB, 256, 0, side>>>(cnt, cur, bsum);
    k_scan_bsum<<<1, 128, 0, side>>>(bsum, bscan);
    k_scan_add<<<NB, 256, 0, side>>>(cur, bscan, cnt, dinv);
    k_fill<<<(GE + B - 1) / B, B, 0, side>>>(src, dst, dinv, cur, cnt,
                                             csrc, cdst, cnrm);
    cudaEventRecord(evJ, side);                 // build done

    // ---- main stream: gemm1 runs concurrently with the build
    k_gemm1<<<(GN + G1_ROWS - 1) / G1_ROWS, 256>>>(x, pos, W1, hw1);

    // Join: everything below needs the build outputs.
    cudaStreamWaitEvent(0, evJ, 0);

    // ---- layer 1
    k_init1<<<(GN * 16 + B - 1) / B, B>>>((const float4*)hw1, (float4*)agg1, b1, dinv);
    k_agg_seg<4, 256><<<GE / 256, 256>>>((const float4*)hw1, (float4*)agg1,
                                         csrc, cdst, cnrm);

    // ---- layer 2 (ReLU fused into gemm2 smem load; z init fused in epilogue)
    k_gemm2<<<(GN + G2_ROWS - 1) / G2_ROWS, 256>>>(agg1, W2, b2, dinv, hw2, z);
    k_agg_seg<3, 512><<<GE / 512, 256>>>((const float4*)hw2, (float4*)z,
                                         csrc, cdst, cnrm);

    // ---- link-prediction head (fused wab+pred)
    k_pred<<<(GEL + B - 1) / B, B>>>(z, Wl, bl, sl, dl, pred);
}